// round 1
// baseline (speedup 1.0000x reference)
#include <cuda_runtime.h>

// Problem constants (fixed by the dataset)
#define P        576          // feature columns
#define P4       144          // P / 4 (float4 groups per row)
#define NB       444          // K1 grid: 148 SMs * 3 CTAs (1 wave @ 576 thr/CTA)
#define NB2      37           // K2 grid (444 = 37 * 12)
#define BPB      12           // partials folded per K2 block

// Deterministic scratch (no atomics): rule-compliant __device__ globals.
__device__ float g_p1[NB * P];
__device__ float g_p2[NB * P];
__device__ float g_m1[NB2 * P];
__device__ float g_m2[NB2 * P];

// ---------------------------------------------------------------------------
// K1: streaming one-pass reduction of X. Block b handles rows r with
// (r mod 4) == ty and row-group striding; thread (tx,ty) owns columns
// 4*tx .. 4*tx+3 via a single float4 load per row -> perfectly coalesced
// (144 consecutive float4 = 2304B contiguous per warp-group row read).
// ---------------------------------------------------------------------------
__global__ __launch_bounds__(P, 3)
void k1_reduce(const float* __restrict__ X, int n_rows) {
    const int tx = threadIdx.x % P4;     // float4 column group
    const int ty = threadIdx.x / P4;     // row phase 0..3
    const float4* __restrict__ X4 = reinterpret_cast<const float4*>(X);

    float s1x = 0.f, s1y = 0.f, s1z = 0.f, s1w = 0.f;
    float s2x = 0.f, s2y = 0.f, s2z = 0.f, s2w = 0.f;

    #pragma unroll 4
    for (int r = blockIdx.x * 4 + ty; r < n_rows; r += NB * 4) {
        float4 v = __ldg(&X4[r * P4 + tx]);
        s1x += v.x; s1y += v.y; s1z += v.z; s1w += v.w;
        s2x += v.x * v.x; s2y += v.y * v.y;
        s2z += v.z * v.z; s2w += v.w * v.w;
    }

    __shared__ float sh[4 * P];
    const int cbase = tx * 4;
    const int c = threadIdx.x;

    // reduce S1 across the 4 row phases
    sh[ty * P + cbase + 0] = s1x;
    sh[ty * P + cbase + 1] = s1y;
    sh[ty * P + cbase + 2] = s1z;
    sh[ty * P + cbase + 3] = s1w;
    __syncthreads();
    g_p1[blockIdx.x * P + c] = sh[c] + sh[P + c] + sh[2 * P + c] + sh[3 * P + c];
    __syncthreads();

    // reduce S2
    sh[ty * P + cbase + 0] = s2x;
    sh[ty * P + cbase + 1] = s2y;
    sh[ty * P + cbase + 2] = s2z;
    sh[ty * P + cbase + 3] = s2w;
    __syncthreads();
    g_p2[blockIdx.x * P + c] = sh[c] + sh[P + c] + sh[2 * P + c] + sh[3 * P + c];
}

// ---------------------------------------------------------------------------
// K2: fold 444 partial rows -> 37 (coalesced: consecutive threads read
// consecutive columns).
// ---------------------------------------------------------------------------
__global__ __launch_bounds__(P)
void k2_fold(void) {
    const int c = threadIdx.x;
    const int g = blockIdx.x;
    float a = 0.f, b = 0.f;
    #pragma unroll
    for (int i = 0; i < BPB; ++i) {
        const int bb = g * BPB + i;
        a += g_p1[bb * P + c];
        b += g_p2[bb * P + c];
    }
    g_m1[g * P + c] = a;
    g_m2[g * P + c] = b;
}

// ---------------------------------------------------------------------------
// K3: final fold (37 -> 1), cumulant finalize, and projection (cum - mu) @ W.
// Single block, 576 threads, block-wide float4 reduction into out[0..3].
// ---------------------------------------------------------------------------
__global__ __launch_bounds__(P)
void k3_finalize(const float* __restrict__ mu, const float* __restrict__ W,
                 float* __restrict__ out, int n_rows) {
    const int c = threadIdx.x;

    float S1 = 0.f, S2 = 0.f;
    #pragma unroll
    for (int g = 0; g < NB2; ++g) {
        S1 += g_m1[g * P + c];
        S2 += g_m2[g * P + c];
    }
    const float inv = 1.0f / (float)n_rows;
    const float m    = S1 * inv;
    const float mom2 = S2 * inv - m * m;   // exact: mean((x-m)^2) = S2/N - m^2
    // mom1 = mean(x - m) == 0 exactly with m = S1/N

    const int j0 = 3 * c;
    const float cm0 = m    - mu[j0 + 0];
    const float cm1 = 0.f  - mu[j0 + 1];
    const float cm2 = mom2 - mu[j0 + 2];

    const float* __restrict__ w = W + j0 * 4;   // W is (1728, 4) row-major
    float4 acc;
    acc.x = cm0 * w[0] + cm1 * w[4] + cm2 * w[8];
    acc.y = cm0 * w[1] + cm1 * w[5] + cm2 * w[9];
    acc.z = cm0 * w[2] + cm1 * w[6] + cm2 * w[10];
    acc.w = cm0 * w[3] + cm1 * w[7] + cm2 * w[11];

    __shared__ float4 red[P];
    red[c] = acc;
    __syncthreads();

    // 576 = 512 + 64: fold the tail, then power-of-2 tree.
    if (c < 64) {
        float4 o = red[c + 512];
        red[c].x += o.x; red[c].y += o.y; red[c].z += o.z; red[c].w += o.w;
    }
    __syncthreads();
    for (int s = 256; s >= 1; s >>= 1) {
        if (c < s) {
            float4 o = red[c + s];
            red[c].x += o.x; red[c].y += o.y; red[c].z += o.z; red[c].w += o.w;
        }
        __syncthreads();
    }
    if (c == 0) {
        out[0] = red[0].x;
        out[1] = red[0].y;
        out[2] = red[0].z;
        out[3] = red[0].w;
    }
}

extern "C" void kernel_launch(void* const* d_in, const int* in_sizes, int n_in,
                              void* d_out, int out_size) {
    const float* X  = (const float*)d_in[0];   // (N_ROWS, 576) fp32
    const float* mu = (const float*)d_in[1];   // (1728,)
    const float* W  = (const float*)d_in[2];   // (1728, 4)
    float* out = (float*)d_out;                // (1, 4) fp32

    const int n_rows = in_sizes[0] / P;        // 200000

    k1_reduce<<<NB, P>>>(X, n_rows);
    k2_fold<<<NB2, P>>>();
    k3_finalize<<<1, P>>>(mu, W, out, n_rows);
}